// round 6
// baseline (speedup 1.0000x reference)
#include <cuda_runtime.h>
#include <cstdint>
#include <cstddef>

#define NB  2
#define NH  12
#define HD  64
#define SEQ 2048
#define EMB 768
#define NCOL 2304  // 3*NH*HD

// Scratch. Q and K stored TRANSPOSED (b,h,d,n); V natural (b,h,n,d).
__device__ float g_Q[NB * NH * HD * SEQ];
__device__ float g_K[NB * NH * HD * SEQ];
__device__ float g_V[NB * NH * SEQ * HD];

typedef unsigned long long ull;

static __device__ __forceinline__ ull pack2(float lo, float hi) {
    ull r; asm("mov.b64 %0, {%1, %2};" : "=l"(r) : "f"(lo), "f"(hi)); return r;
}
static __device__ __forceinline__ void unpack2(float& lo, float& hi, ull v) {
    asm("mov.b64 {%0, %1}, %2;" : "=f"(lo), "=f"(hi) : "l"(v));
}
static __device__ __forceinline__ void fma2(ull& d, ull a, ull b) {
    asm("fma.rn.f32x2 %0, %1, %2, %0;" : "+l"(d) : "l"(a), "l"(b));
}

// ============================================================================
// Kernel 1: fused QKV GEMM + bias + scatter (Q,K transposed; V natural).
// ============================================================================
__global__ __launch_bounds__(256, 2)
void qkv_gemm_kernel(const float* __restrict__ z, const float* __restrict__ W,
                     const float* __restrict__ bias)
{
    __shared__ float As[16][132];
    __shared__ float Bs[16][128];

    const int tid = threadIdx.x;
    const int tx = tid & 15;
    const int ty = tid >> 4;
    const int m0 = blockIdx.y * 128;
    const int n0 = blockIdx.x * 128;

    ull acc[8][4];
#pragma unroll
    for (int i = 0; i < 8; i++)
#pragma unroll
        for (int j = 0; j < 4; j++) acc[i][j] = 0ull;

    float4 aL[2], bL[2];
#pragma unroll
    for (int i = 0; i < 2; i++) {
        int f = tid * 2 + i;
        aL[i] = *(const float4*)&z[(size_t)(m0 + (f >> 2)) * EMB + ((f & 3) << 2)];
        int e = tid + (i << 8);
        bL[i] = *(const float4*)&W[(size_t)(e >> 5) * NCOL + n0 + ((e & 31) << 2)];
    }

    for (int kt = 0; kt < 48; kt++) {
#pragma unroll
        for (int i = 0; i < 2; i++) {
            int f = tid * 2 + i;
            int row = f >> 2, kb = (f & 3) << 2;
            As[kb + 0][row] = aL[i].x; As[kb + 1][row] = aL[i].y;
            As[kb + 2][row] = aL[i].z; As[kb + 3][row] = aL[i].w;
            int e = tid + (i << 8);
            *(float4*)&Bs[e >> 5][(e & 31) << 2] = bL[i];
        }
        __syncthreads();

        if (kt < 47) {
            int kbase = (kt + 1) * 16;
#pragma unroll
            for (int i = 0; i < 2; i++) {
                int f = tid * 2 + i;
                aL[i] = *(const float4*)&z[(size_t)(m0 + (f >> 2)) * EMB + kbase + ((f & 3) << 2)];
                int e = tid + (i << 8);
                bL[i] = *(const float4*)&W[(size_t)(kbase + (e >> 5)) * NCOL + n0 + ((e & 31) << 2)];
            }
        }

#pragma unroll
        for (int kk = 0; kk < 16; kk++) {
            float4 a0 = *(const float4*)&As[kk][ty << 3];
            float4 a1 = *(const float4*)&As[kk][(ty << 3) + 4];
            ulonglong2 b0 = *(const ulonglong2*)&Bs[kk][tx << 3];
            ulonglong2 b1 = *(const ulonglong2*)&Bs[kk][(tx << 3) + 4];
            float av[8] = {a0.x, a0.y, a0.z, a0.w, a1.x, a1.y, a1.z, a1.w};
#pragma unroll
            for (int i = 0; i < 8; i++) {
                ull ad = pack2(av[i], av[i]);
                fma2(acc[i][0], ad, b0.x);
                fma2(acc[i][1], ad, b0.y);
                fma2(acc[i][2], ad, b1.x);
                fma2(acc[i][3], ad, b1.y);
            }
        }
        __syncthreads();
    }

    const int mrow = m0 + (ty << 3);
#pragma unroll
    for (int i = 0; i < 8; i++) {
        int row = mrow + i;
        int bb = row >> 11;
        int nn = row & 2047;
#pragma unroll
        for (int j = 0; j < 4; j++) {
            float lo, hi;
            unpack2(lo, hi, acc[i][j]);
            int c0 = n0 + (tx << 3) + j * 2;
#pragma unroll
            for (int u = 0; u < 2; u++) {
                int c = c0 + u;
                float v = (u == 0 ? lo : hi) + bias[c];
                int h = c / 192;
                int rem = c - h * 192;
                int d = rem / 3;
                int s = rem - d * 3;
                size_t bhf = (size_t)(bb * NH + h);
                if (s == 0)      g_K[(bhf * HD + d) * SEQ + nn] = v;
                else if (s == 1) g_V[(bhf * SEQ + nn) * HD + d] = v;
                else             g_Q[(bhf * HD + d) * SEQ + nn] = v;
            }
        }
    }
}

// ============================================================================
// Kernel 2: flash-style attention, fp32 f32x2, no-max softmax (logits bounded;
// shift cancels in O/l). Reference bug preserved: 0.125 applied post-softmax.
//
// 256 threads, BM=64 q, BN=128 k/tile, 16 tiles, 2 CTAs/SM.
// S phase:  warp qg = tid>>5 (8 q-rows), lane kg (4 k-cols). Pairs over q.
// P staged K-MAJOR as q-pairs with XOR swizzle: Ps[k][ (qquad ^ ((k>>2)&7)) ]
//   (address transform; reads apply the same XOR -> conflict-free LDS.128).
// PV phase: warp -> (k-half = wid&1, d-slice = (wid>>1)*16); lane ->
//   (qquad = lane&15, dhalf = lane>>4). Pairs over q: each V-dup feeds 2 fma2.
//   Cross-half O reduced via smem at the end.
// Smem: Qs 64x64, Ks 64x128, Vs 128x64, Ps 128x64 = 112 KB -> 2 CTAs/SM.
// ============================================================================
__global__ __launch_bounds__(256, 2)
void attn_kernel(float* __restrict__ out)
{
    extern __shared__ float sm[];
    float* Qs = sm;                          // [d][q]  64x64 (later: Ls)
    float* Ks = sm + 64 * 64;                // [d][k]  64x128 (later: O staging)
    float* Vs = sm + 64 * 64 + 64 * 128;     // [k][d]  128x64
    float* Ps = Vs + 128 * 64;               // [k][qpairs] 128x64, swizzled

    const int tid = threadIdx.x;
    const int lane = tid & 31;
    const int wid  = tid >> 5;
    const int qg = wid;                 // S: q rows [qg*8, qg*8+8)
    const int kg = lane;                // S: k cols [kg*4, kg*4+4)
    const int kh    = wid & 1;          // PV: k half
    const int dbase = ((wid >> 1) << 4) + ((lane >> 4) << 3);  // 8-d slice
    const int qquad = lane & 15;        // PV: q quad [qquad*4, +4)
    const int q0 = blockIdx.x << 6;
    const int bh = blockIdx.y;

    const float* QT = g_Q + (size_t)bh * HD * SEQ;
    const float* KT = g_K + (size_t)bh * HD * SEQ;
    const float* Vg = g_V + (size_t)bh * SEQ * HD;

    // Q tile: Qs[d][q]
    {
        int d = tid >> 4;
        int c = (tid & 15) << 2;
#pragma unroll
        for (int i = 0; i < 4; i++)
            *(float4*)&Qs[(d + i * 16) * 64 + c] =
                *(const float4*)&QT[(size_t)(d + i * 16) * SEQ + q0 + c];
    }

    ull o2[2][8];   // [q-pair pr][d j] : pairs (q, q+1), q = 4*qquad + 2*pr
#pragma unroll
    for (int pr = 0; pr < 2; pr++)
#pragma unroll
        for (int j = 0; j < 8; j++) o2[pr][j] = 0ull;
    float lsum[8] = {0.f, 0.f, 0.f, 0.f, 0.f, 0.f, 0.f, 0.f};

    for (int kt = 0; kt < 16; kt++) {
        __syncthreads();
        const int k0 = kt << 7;

        // K tile: Ks[d][k] 64x128
        {
            int d = tid >> 5;
            int c = lane << 2;
#pragma unroll
            for (int i = 0; i < 8; i++)
                *(float4*)&Ks[(d + i * 8) * 128 + c] =
                    *(const float4*)&KT[(size_t)(d + i * 8) * SEQ + k0 + c];
        }
        // V tile: Vs[k][d] 128x64
        {
            int r = tid >> 4;
            int c = (tid & 15) << 2;
#pragma unroll
            for (int i = 0; i < 8; i++)
                *(float4*)&Vs[(r + i * 16) * 64 + c] =
                    *(const float4*)&Vg[(size_t)(k0 + r + i * 16) * HD + c];
        }
        __syncthreads();

        // S = Q^T K : 8q x 4k per thread, pairs over q.
        ull sacc[4][4];   // [k j][q pair p]
#pragma unroll
        for (int j = 0; j < 4; j++)
#pragma unroll
            for (int p = 0; p < 4; p++) sacc[j][p] = 0ull;

        const float* qb = Qs + (qg << 3);
        const float* kb = Ks + (kg << 2);
#pragma unroll 4
        for (int d = 0; d < 64; d++) {
            ulonglong2 qA = *(const ulonglong2*)(qb + d * 64);
            ulonglong2 qB = *(const ulonglong2*)(qb + d * 64 + 4);
            float4 kA = *(const float4*)(kb + d * 128);
            ull qp[4] = {qA.x, qA.y, qB.x, qB.y};
            float kf[4] = {kA.x, kA.y, kA.z, kA.w};
#pragma unroll
            for (int j = 0; j < 4; j++) {
                ull kd = pack2(kf[j], kf[j]);
#pragma unroll
                for (int p = 0; p < 4; p++) fma2(sacc[j][p], qp[p], kd);
            }
        }

        // exp (no max shift), accumulate l, stage P k-major q-pairs, swizzled.
        const int gsw = kg & 7;
#pragma unroll
        for (int p = 0; p < 4; p++) {
            const int qq = (qg << 1) + (p >> 1);   // qquad of this pair
            const int pr = p & 1;
#pragma unroll
            for (int j = 0; j < 4; j++) {
                float s0, s1;
                unpack2(s0, s1, sacc[j][p]);
                float e0 = __expf(s0);
                float e1 = __expf(s1);
                lsum[2 * p]     += e0;
                lsum[2 * p + 1] += e1;
                int krow = (kg << 2) + j;
                *(ull*)&Ps[krow * 64 + ((qq ^ gsw) << 2) + (pr << 1)] = pack2(e0, e1);
            }
        }
        __syncthreads();

        // O += P V : per warp (k-half, 16 d); per lane (qquad, 8 d).
        const int kb2 = kh << 6;
#pragma unroll 2
        for (int k = 0; k < 64; k++) {
            int kk = kb2 + k;
            int g = (kk >> 2) & 7;
            ulonglong2 pp = *(const ulonglong2*)&Ps[kk * 64 + ((qquad ^ g) << 2)];
            float4 va = *(const float4*)&Vs[kk * 64 + dbase];
            float4 vb = *(const float4*)&Vs[kk * 64 + dbase + 4];
            float vf[8] = {va.x, va.y, va.z, va.w, vb.x, vb.y, vb.z, vb.w};
#pragma unroll
            for (int j = 0; j < 8; j++) {
                ull vd = pack2(vf[j], vf[j]);
                fma2(o2[0][j], pp.x, vd);
                fma2(o2[1][j], pp.y, vd);
            }
        }
    }

    // l: reduce across 32 lanes (kg spans all 128 k per warp), stash in Qs.
#pragma unroll
    for (int qi = 0; qi < 8; qi++) {
#pragma unroll
        for (int off = 16; off > 0; off >>= 1)
            lsum[qi] += __shfl_xor_sync(0xffffffffu, lsum[qi], off);
    }
    if (lane == 0) {
#pragma unroll
        for (int qi = 0; qi < 8; qi++) Qs[(qg << 3) + qi] = lsum[qi];
    }

    // kh=1 warps stage partial O into smem (reuse Ks): Osm[d][q] pitch 66.
    if (kh == 1) {
#pragma unroll
        for (int pr = 0; pr < 2; pr++)
#pragma unroll
            for (int j = 0; j < 8; j++)
                *(ull*)&Ks[(dbase + j) * 66 + (qquad << 2) + (pr << 1)] = o2[pr][j];
    }
    __syncthreads();

    if (kh == 0) {
        const int b = bh / NH;
        const int h = bh - b * NH;
#pragma unroll
        for (int pr = 0; pr < 2; pr++) {
            int q = (qquad << 2) + (pr << 1);
            float inv0 = 0.125f / Qs[q];
            float inv1 = 0.125f / Qs[q + 1];
            float w0[8], w1[8];
#pragma unroll
            for (int j = 0; j < 8; j++) {
                float mlo, mhi, plo, phi;
                unpack2(mlo, mhi, o2[pr][j]);
                unpack2(plo, phi, *(const ull*)&Ks[(dbase + j) * 66 + (qquad << 2) + (pr << 1)]);
                w0[j] = (mlo + plo) * inv0;
                w1[j] = (mhi + phi) * inv1;
            }
            float* dst0 = out + ((size_t)(b * SEQ + q0 + q)) * EMB + h * HD + dbase;
            float* dst1 = dst0 + EMB;
            *(float4*)dst0       = make_float4(w0[0], w0[1], w0[2], w0[3]);
            *(float4*)(dst0 + 4) = make_float4(w0[4], w0[5], w0[6], w0[7]);
            *(float4*)dst1       = make_float4(w1[0], w1[1], w1[2], w1[3]);
            *(float4*)(dst1 + 4) = make_float4(w1[4], w1[5], w1[6], w1[7]);
        }
    }
}

// ============================================================================
extern "C" void kernel_launch(void* const* d_in, const int* in_sizes, int n_in,
                              void* d_out, int out_size)
{
    const float* z = nullptr;
    const float* W = nullptr;
    const float* bias = nullptr;
    for (int i = 0; i < n_in; i++) {
        if (in_sizes[i] == NB * SEQ * EMB)      z = (const float*)d_in[i];
        else if (in_sizes[i] == EMB * NCOL)     W = (const float*)d_in[i];
        else if (in_sizes[i] == NCOL)           bias = (const float*)d_in[i];
    }
    float* out = (float*)d_out;

    dim3 g1(NCOL / 128, (NB * SEQ) / 128);   // (18, 32)
    qkv_gemm_kernel<<<g1, 256>>>(z, W, bias);

    const int smem_bytes = (64 * 64 + 64 * 128 + 128 * 64 + 128 * 64)
                           * (int)sizeof(float);  // 114688
    cudaFuncSetAttribute(attn_kernel, cudaFuncAttributeMaxDynamicSharedMemorySize,
                         smem_bytes);
    dim3 g2(SEQ / 64, NB * NH);              // (32, 24)
    attn_kernel<<<g2, 256, smem_bytes>>>(out);
}

// round 8
// speedup vs baseline: 1.2988x; 1.2988x over previous
#include <cuda_runtime.h>
#include <cuda_bf16.h>
#include <cstdint>
#include <cstddef>

#define NB  2
#define NH  12
#define HD  64
#define SEQ 2048
#define EMB 768
#define NCOL 2304  // 3*NH*HD
#define MROWS (NB * SEQ)   // 4096

// Scratch. Q and K stored TRANSPOSED (b,h,d,n); V natural (b,h,n,d).
__device__ float g_Q[NB * NH * HD * SEQ];
__device__ float g_K[NB * NH * HD * SEQ];
__device__ float g_V[NB * NH * SEQ * HD];
// bf16 split operands for the QKV MMA.
__device__ __nv_bfloat16 g_zh[MROWS * EMB];
__device__ __nv_bfloat16 g_zl[MROWS * EMB];
__device__ __nv_bfloat16 g_WhT[NCOL * EMB];   // [n][k] = W[k][n] hi
__device__ __nv_bfloat16 g_WlT[NCOL * EMB];   // lo

typedef unsigned long long ull;

static __device__ __forceinline__ ull pack2(float lo, float hi) {
    ull r; asm("mov.b64 %0, {%1, %2};" : "=l"(r) : "f"(lo), "f"(hi)); return r;
}
static __device__ __forceinline__ void unpack2(float& lo, float& hi, ull v) {
    asm("mov.b64 {%0, %1}, %2;" : "=f"(lo), "=f"(hi) : "l"(v));
}
static __device__ __forceinline__ void fma2(ull& d, ull a, ull b) {
    asm("fma.rn.f32x2 %0, %1, %2, %0;" : "+l"(d) : "l"(a), "l"(b));
}
static __device__ __forceinline__ uint32_t smem_u32(const void* p) {
    uint32_t a;
    asm("{ .reg .u64 t; cvta.to.shared.u64 t, %1; cvt.u32.u64 %0, t; }"
        : "=r"(a) : "l"(p));
    return a;
}

// ---------------- HMMA helpers (mma.sync, works on plain sm_103 target) ----
#define LDM_X4(r, a) \
    asm volatile("ldmatrix.sync.aligned.m8n8.x4.shared.b16 {%0,%1,%2,%3}, [%4];" \
        : "=r"((r)[0]), "=r"((r)[1]), "=r"((r)[2]), "=r"((r)[3]) : "r"(a))
#define LDM_X2(r, a) \
    asm volatile("ldmatrix.sync.aligned.m8n8.x2.shared.b16 {%0,%1}, [%2];" \
        : "=r"((r)[0]), "=r"((r)[1]) : "r"(a))
#define MMA_BF16(d, a, b) \
    asm volatile("mma.sync.aligned.m16n8k16.row.col.f32.bf16.bf16.f32 " \
        "{%0,%1,%2,%3}, {%4,%5,%6,%7}, {%8,%9}, {%0,%1,%2,%3};" \
        : "+f"((d)[0]), "+f"((d)[1]), "+f"((d)[2]), "+f"((d)[3]) \
        : "r"((a)[0]), "r"((a)[1]), "r"((a)[2]), "r"((a)[3]), \
          "r"((b)[0]), "r"((b)[1]))

// ============================================================================
// Kernel A: z fp32 -> (zh, zl) bf16 split. Vectorized by 4.
// ============================================================================
__global__ void convert_z_kernel(const float* __restrict__ z)
{
    int i4 = blockIdx.x * 256 + threadIdx.x;            // 786432 quads
    float4 v = ((const float4*)z)[i4];
    __nv_bfloat16 h0 = __float2bfloat16(v.x);
    __nv_bfloat16 h1 = __float2bfloat16(v.y);
    __nv_bfloat16 h2 = __float2bfloat16(v.z);
    __nv_bfloat16 h3 = __float2bfloat16(v.w);
    __nv_bfloat162* zh2 = (__nv_bfloat162*)g_zh;
    __nv_bfloat162* zl2 = (__nv_bfloat162*)g_zl;
    zh2[i4 * 2]     = __nv_bfloat162(h0, h1);
    zh2[i4 * 2 + 1] = __nv_bfloat162(h2, h3);
    zl2[i4 * 2]     = __nv_bfloat162(__float2bfloat16(v.x - __bfloat162float(h0)),
                                     __float2bfloat16(v.y - __bfloat162float(h1)));
    zl2[i4 * 2 + 1] = __nv_bfloat162(__float2bfloat16(v.z - __bfloat162float(h2)),
                                     __float2bfloat16(v.w - __bfloat162float(h3)));
}

// ============================================================================
// Kernel B: W[768][2304] fp32 -> WhT/WlT[2304][768] bf16 (transpose + split).
// ============================================================================
__global__ void convert_w_kernel(const float* __restrict__ W)
{
    __shared__ float t[32][33];
    const int n0 = blockIdx.x * 32;
    const int k0 = blockIdx.y * 32;
    const int tx = threadIdx.x, ty = threadIdx.y;   // 32 x 8
#pragma unroll
    for (int i = 0; i < 4; i++)
        t[ty + 8 * i][tx] = W[(size_t)(k0 + ty + 8 * i) * NCOL + n0 + tx];
    __syncthreads();
#pragma unroll
    for (int i = 0; i < 4; i++) {
        float v = t[tx][ty + 8 * i];
        __nv_bfloat16 h = __float2bfloat16(v);
        size_t o = (size_t)(n0 + ty + 8 * i) * EMB + k0 + tx;
        g_WhT[o] = h;
        g_WlT[o] = __float2bfloat16(v - __bfloat162float(h));
    }
}

// ============================================================================
// Kernel C: QKV GEMM via HMMA mma.sync, bf16x3 split (AhBh + AhBl + AlBh).
// CTA tile 128x128, 8 warps (2M x 4N), warp tile 64x32 (4 m16 x 4 n8 frags).
// K = 768 in 12 chunks of 64; smem pitch 72 bf16 (144 B) -> ldmatrix phases
// hit 16r mod 128: conflict-free.
// Epilogue: + bias, scatter to g_Q/g_K (d-major) and g_V.
// ============================================================================
#define AP 72   // smem pitch in bf16

__global__ __launch_bounds__(256, 1)
void qkv_mma_kernel(const float* __restrict__ bias)
{
    extern __shared__ __nv_bfloat16 smb[];
    __nv_bfloat16* sAh = smb;                 // [128][72]
    __nv_bfloat16* sAl = smb + 128 * AP;
    __nv_bfloat16* sBh = smb + 2 * 128 * AP;
    __nv_bfloat16* sBl = smb + 3 * 128 * AP;

    const int tid  = threadIdx.x;
    const int lane = tid & 31;
    const int wid  = tid >> 5;
    const int wm = (wid >> 2) << 6;    // 0 / 64
    const int wn = (wid & 3) << 5;     // 0,32,64,96
    const int m0 = blockIdx.y * 128;
    const int n0 = blockIdx.x * 128;

    const uint32_t uAh = smem_u32(sAh), uAl = smem_u32(sAl);
    const uint32_t uBh = smem_u32(sBh), uBl = smem_u32(sBl);

    float acc[4][4][4];
#pragma unroll
    for (int mt = 0; mt < 4; mt++)
#pragma unroll
        for (int nt = 0; nt < 4; nt++)
#pragma unroll
            for (int e = 0; e < 4; e++) acc[mt][nt][e] = 0.f;

    // ldmatrix base offsets (bytes) for this lane
    const uint32_t a_off = (uint32_t)((wm + (lane & 15)) * AP + ((lane >> 4) << 3)) * 2;
    const uint32_t b_off = (uint32_t)((wn + (lane & 7)) * AP + (((lane >> 3) & 1) << 3)) * 2;

    for (int kc = 0; kc < 12; kc++) {
        const int kb = kc * 64;
        __syncthreads();   // previous chunk's ldmatrix reads complete
#pragma unroll
        for (int j = 0; j < 4; j++) {
            int idx = tid + j * 256;        // 1024 uint4 per matrix
            int r = idx >> 3, c = idx & 7;  // row, uint4-within-row
            size_t ga = (size_t)(m0 + r) * EMB + kb + c * 8;
            size_t gb = (size_t)(n0 + r) * EMB + kb + c * 8;
            uint32_t so = (uint32_t)(r * AP + c * 8) * 2;
            *(uint4*)((char*)sAh + so) = *(const uint4*)&g_zh[ga];
            *(uint4*)((char*)sAl + so) = *(const uint4*)&g_zl[ga];
            *(uint4*)((char*)sBh + so) = *(const uint4*)&g_WhT[gb];
            *(uint4*)((char*)sBl + so) = *(const uint4*)&g_WlT[gb];
        }
        __syncthreads();

#pragma unroll
        for (int ks = 0; ks < 4; ks++) {
            const uint32_t kof = (uint32_t)(ks * 16) * 2;
            uint32_t ah[4][4], al[4][4], bh[4][2], bl[4][2];
#pragma unroll
            for (int mt = 0; mt < 4; mt++) {
                uint32_t ad = a_off + kof + (uint32_t)(mt * 16 * AP) * 2;
                LDM_X4(ah[mt], uAh + ad);
                LDM_X4(al[mt], uAl + ad);
            }
#pragma unroll
            for (int nt = 0; nt < 4; nt++) {
                uint32_t bd = b_off + kof + (uint32_t)(nt * 8 * AP) * 2;
                LDM_X2(bh[nt], uBh + bd);
                LDM_X2(bl[nt], uBl + bd);
            }
#pragma unroll
            for (int mt = 0; mt < 4; mt++)
#pragma unroll
                for (int nt = 0; nt < 4; nt++) {
                    MMA_BF16(acc[mt][nt], ah[mt], bh[nt]);
                    MMA_BF16(acc[mt][nt], ah[mt], bl[nt]);
                    MMA_BF16(acc[mt][nt], al[mt], bh[nt]);
                }
        }
    }

    // Epilogue: bias + scatter. Fragment layout: e0: (g, 2t), e1: (g, 2t+1),
    // e2: (g+8, 2t), e3: (g+8, 2t+1); g = lane>>2, t = lane&3.
    const int g = lane >> 2;
    const int t2 = (lane & 3) << 1;
#pragma unroll
    for (int mt = 0; mt < 4; mt++) {
#pragma unroll
        for (int e2i = 0; e2i < 2; e2i++) {          // row half (e<2 / e>=2)
            int mrow = m0 + wm + mt * 16 + g + e2i * 8;
            int bb = mrow >> 11;
            int nn = mrow & 2047;
            size_t bhf_base = (size_t)(bb * NH);
#pragma unroll
            for (int nt = 0; nt < 4; nt++) {
#pragma unroll
                for (int u = 0; u < 2; u++) {
                    int c = n0 + wn + nt * 8 + t2 + u;
                    float v = acc[mt][nt][e2i * 2 + u] + bias[c];
                    int h = c / 192;
                    int rem = c - h * 192;
                    int d = rem / 3;
                    int s = rem - d * 3;
                    size_t bhf = bhf_base + h;
                    if (s == 0)      g_K[(bhf * HD + d) * SEQ + nn] = v;
                    else if (s == 1) g_V[(bhf * SEQ + nn) * HD + d] = v;
                    else             g_Q[(bhf * HD + d) * SEQ + nn] = v;
                }
            }
        }
    }
}

// ============================================================================
// Kernel D: attention — R3 structure (best measured), conflict-free d-major
// fills. Reference bug preserved: 1/sqrt(D)=0.125 applied AFTER softmax.
// ============================================================================
__global__ __launch_bounds__(128, 3)
void attn_kernel(float* __restrict__ out)
{
    extern __shared__ float sm[];
    float* Qs = sm;                 // [64 d][68]  ([d][q])
    float* Ks = sm + 64 * 68;       // [64 d][68]  ([d][k])
    float* Vs = sm + 2 * 64 * 68;   // [64 k][68]  ([k][d])
    float* Ps = sm + 3 * 64 * 68;   // [64 k][68]  ([k][q])

    const int tid = threadIdx.x;
    const int qg = tid >> 3;
    const int kg = tid & 7;
    const int q0 = blockIdx.x << 6;
    const int bh = blockIdx.y;

    const float* QT = g_Q + (size_t)bh * HD * SEQ;
    const float* KT = g_K + (size_t)bh * HD * SEQ;
    const float* Vg = g_V + (size_t)bh * SEQ * HD;

#pragma unroll
    for (int i = 0; i < 8; i++) {
        int f = tid + (i << 7);
        int d = f >> 4;
        int c = (f & 15) << 2;
        *(float4*)&Qs[d * 68 + c] = *(const float4*)&QT[(size_t)d * SEQ + q0 + c];
    }

    ull o2[4][4];
#pragma unroll
    for (int qi = 0; qi < 4; qi++)
#pragma unroll
        for (int j = 0; j < 4; j++) o2[qi][j] = 0ull;
    float m_r[4] = {-3.0e38f, -3.0e38f, -3.0e38f, -3.0e38f};
    float l_r[4] = {0.f, 0.f, 0.f, 0.f};

    for (int kt = 0; kt < 32; kt++) {
        __syncthreads();
        const int k0 = kt << 6;
#pragma unroll
        for (int i = 0; i < 8; i++) {
            int f = tid + (i << 7);
            int d = f >> 4;
            int c = (f & 15) << 2;
            *(float4*)&Ks[d * 68 + c] = *(const float4*)&KT[(size_t)d * SEQ + k0 + c];
            *(float4*)&Vs[d * 68 + c] = *(const float4*)&Vg[(size_t)(k0 + d) * HD + c];
        }
        __syncthreads();

        ull sacc[4][4];
#pragma unroll
        for (int qi = 0; qi < 4; qi++)
#pragma unroll
            for (int j = 0; j < 4; j++) sacc[qi][j] = 0ull;

        const float* qbase = Qs + (qg << 2);
        const float* kbase = Ks + (kg << 3);
#pragma unroll 8
        for (int d = 0; d < 64; d++) {
            float4 qv = *(const float4*)(qbase + d * 68);
            ulonglong2 kA = *(const ulonglong2*)(kbase + d * 68);
            ulonglong2 kB = *(const ulonglong2*)(kbase + d * 68 + 4);
            float qa[4] = {qv.x, qv.y, qv.z, qv.w};
#pragma unroll
            for (int qi = 0; qi < 4; qi++) {
                ull qd = pack2(qa[qi], qa[qi]);
                fma2(sacc[qi][0], qd, kA.x);
                fma2(sacc[qi][1], qd, kA.y);
                fma2(sacc[qi][2], qd, kB.x);
                fma2(sacc[qi][3], qd, kB.y);
            }
        }

        float p[4][8];
#pragma unroll
        for (int qi = 0; qi < 4; qi++) {
            float s[8];
            unpack2(s[0], s[1], sacc[qi][0]);
            unpack2(s[2], s[3], sacc[qi][1]);
            unpack2(s[4], s[5], sacc[qi][2]);
            unpack2(s[6], s[7], sacc[qi][3]);
            float mx = s[0];
#pragma unroll
            for (int j = 1; j < 8; j++) mx = fmaxf(mx, s[j]);
#pragma unroll
            for (int off = 1; off < 8; off <<= 1)
                mx = fmaxf(mx, __shfl_xor_sync(0xffffffffu, mx, off));
            float mn = fmaxf(m_r[qi], mx);
            float sc = __expf(m_r[qi] - mn);
            m_r[qi] = mn;
            float sum = 0.f;
#pragma unroll
            for (int j = 0; j < 8; j++) {
                float e = __expf(s[j] - mn);
                p[qi][j] = e;
                sum += e;
            }
#pragma unroll
            for (int off = 1; off < 8; off <<= 1)
                sum += __shfl_xor_sync(0xffffffffu, sum, off);
            l_r[qi] = l_r[qi] * sc + sum;
            ull sc2 = pack2(sc, sc);
#pragma unroll
            for (int j = 0; j < 4; j++) {
                ull t;
                asm("mul.rn.f32x2 %0, %1, %2;" : "=l"(t) : "l"(o2[qi][j]), "l"(sc2));
                o2[qi][j] = t;
            }
        }
#pragma unroll
        for (int j = 0; j < 8; j++) {
            *(float4*)&Ps[(kg * 8 + j) * 68 + (qg << 2)] =
                make_float4(p[0][j], p[1][j], p[2][j], p[3][j]);
        }
        __syncthreads();

        const float* pbase = Ps + (qg << 2);
        const float* vbase = Vs + (kg << 3);
#pragma unroll 8
        for (int k = 0; k < 64; k++) {
            float4 pv = *(const float4*)(pbase + k * 68);
            ulonglong2 vA = *(const ulonglong2*)(vbase + k * 68);
            ulonglong2 vB = *(const ulonglong2*)(vbase + k * 68 + 4);
            float pa[4] = {pv.x, pv.y, pv.z, pv.w};
#pragma unroll
            for (int qi = 0; qi < 4; qi++) {
                ull pd = pack2(pa[qi], pa[qi]);
                fma2(o2[qi][0], pd, vA.x);
                fma2(o2[qi][1], pd, vA.y);
                fma2(o2[qi][2], pd, vB.x);
                fma2(o2[qi][3], pd, vB.y);
            }
        }
    }

    const int b = bh / NH;
    const int h = bh - b * NH;
#pragma unroll
    for (int qi = 0; qi < 4; qi++) {
        float inv = 0.125f / l_r[qi];
        float v[8];
        unpack2(v[0], v[1], o2[qi][0]);
        unpack2(v[2], v[3], o2[qi][1]);
        unpack2(v[4], v[5], o2[qi][2]);
        unpack2(v[6], v[7], o2[qi][3]);
        int n = q0 + (qg << 2) + qi;
        float* dst = out + ((size_t)(b * SEQ + n)) * EMB + h * HD + (kg << 3);
        *(float4*)dst       = make_float4(v[0] * inv, v[1] * inv, v[2] * inv, v[3] * inv);
        *(float4*)(dst + 4) = make_float4(v[4] * inv, v[5] * inv, v[6] * inv, v[7] * inv);
    }
}

// ============================================================================
extern "C" void kernel_launch(void* const* d_in, const int* in_sizes, int n_in,
                              void* d_out, int out_size)
{
    const float* z = nullptr;
    const float* W = nullptr;
    const float* bias = nullptr;
    for (int i = 0; i < n_in; i++) {
        if (in_sizes[i] == NB * SEQ * EMB)      z = (const float*)d_in[i];
        else if (in_sizes[i] == EMB * NCOL)     W = (const float*)d_in[i];
        else if (in_sizes[i] == NCOL)           bias = (const float*)d_in[i];
    }
    float* out = (float*)d_out;

    convert_z_kernel<<<(MROWS * EMB / 4) / 256, 256>>>(z);
    convert_w_kernel<<<dim3(NCOL / 32, EMB / 32), dim3(32, 8)>>>(W);

    const int mma_smem = 4 * 128 * AP * (int)sizeof(__nv_bfloat16);  // 73728
    cudaFuncSetAttribute(qkv_mma_kernel, cudaFuncAttributeMaxDynamicSharedMemorySize,
                         mma_smem);
    qkv_mma_kernel<<<dim3(NCOL / 128, MROWS / 128), 256, mma_smem>>>(bias);

    const int attn_smem = 4 * 64 * 68 * (int)sizeof(float);  // 69632
    cudaFuncSetAttribute(attn_kernel, cudaFuncAttributeMaxDynamicSharedMemorySize,
                         attn_smem);
    attn_kernel<<<dim3(SEQ / 64, NB * NH), 128, attn_smem>>>(out);
}

// round 9
// speedup vs baseline: 3.2982x; 2.5394x over previous
#include <cuda_runtime.h>
#include <cuda_bf16.h>
#include <cstdint>
#include <cstddef>

#define NB  2
#define NH  12
#define HD  64
#define SEQ 2048
#define EMB 768
#define NCOL 2304  // 3*NH*HD
#define MROWS (NB * SEQ)   // 4096

// bf16 split operands produced by the QKV GEMM epilogue.
// Q, K: [bh][n][d] (row-major per head). V: transposed [bh][d][n].
__device__ __nv_bfloat16 g_Qh[NB * NH * SEQ * HD];
__device__ __nv_bfloat16 g_Ql[NB * NH * SEQ * HD];
__device__ __nv_bfloat16 g_Kh[NB * NH * SEQ * HD];
__device__ __nv_bfloat16 g_Kl[NB * NH * SEQ * HD];
__device__ __nv_bfloat16 g_VTh[NB * NH * HD * SEQ];
__device__ __nv_bfloat16 g_VTl[NB * NH * HD * SEQ];
// bf16 split operands for the QKV MMA inputs.
__device__ __nv_bfloat16 g_zh[MROWS * EMB];
__device__ __nv_bfloat16 g_zl[MROWS * EMB];
__device__ __nv_bfloat16 g_WhT[NCOL * EMB];   // [n][k] = W[k][n] hi
__device__ __nv_bfloat16 g_WlT[NCOL * EMB];   // lo

static __device__ __forceinline__ uint32_t smem_u32(const void* p) {
    uint32_t a;
    asm("{ .reg .u64 t; cvta.to.shared.u64 t, %1; cvt.u32.u64 %0, t; }"
        : "=r"(a) : "l"(p));
    return a;
}

// ---------------- HMMA helpers (mma.sync, plain sm_103 target) ------------
#define LDM_X4(r, a) \
    asm volatile("ldmatrix.sync.aligned.m8n8.x4.shared.b16 {%0,%1,%2,%3}, [%4];" \
        : "=r"((r)[0]), "=r"((r)[1]), "=r"((r)[2]), "=r"((r)[3]) : "r"(a))
#define LDM_X2(r, a) \
    asm volatile("ldmatrix.sync.aligned.m8n8.x2.shared.b16 {%0,%1}, [%2];" \
        : "=r"((r)[0]), "=r"((r)[1]) : "r"(a))
#define MMA_BF16(d, a, b) \
    asm volatile("mma.sync.aligned.m16n8k16.row.col.f32.bf16.bf16.f32 " \
        "{%0,%1,%2,%3}, {%4,%5,%6,%7}, {%8,%9}, {%0,%1,%2,%3};" \
        : "+f"((d)[0]), "+f"((d)[1]), "+f"((d)[2]), "+f"((d)[3]) \
        : "r"((a)[0]), "r"((a)[1]), "r"((a)[2]), "r"((a)[3]), \
          "r"((b)[0]), "r"((b)[1]))

// pack {lo, hi} floats into a bf16x2 register (a -> upper, b -> lower in PTX)
static __device__ __forceinline__ uint32_t cvt_bf16x2(float hi, float lo) {
    uint32_t r;
    asm("cvt.rn.bf16x2.f32 %0, %1, %2;" : "=r"(r) : "f"(hi), "f"(lo));
    return r;
}

// ============================================================================
// Kernel A: z fp32 -> (zh, zl) bf16 split. Vectorized by 4.
// ============================================================================
__global__ void convert_z_kernel(const float* __restrict__ z)
{
    int i4 = blockIdx.x * 256 + threadIdx.x;
    float4 v = ((const float4*)z)[i4];
    __nv_bfloat16 h0 = __float2bfloat16(v.x);
    __nv_bfloat16 h1 = __float2bfloat16(v.y);
    __nv_bfloat16 h2 = __float2bfloat16(v.z);
    __nv_bfloat16 h3 = __float2bfloat16(v.w);
    __nv_bfloat162* zh2 = (__nv_bfloat162*)g_zh;
    __nv_bfloat162* zl2 = (__nv_bfloat162*)g_zl;
    zh2[i4 * 2]     = __nv_bfloat162(h0, h1);
    zh2[i4 * 2 + 1] = __nv_bfloat162(h2, h3);
    zl2[i4 * 2]     = __nv_bfloat162(__float2bfloat16(v.x - __bfloat162float(h0)),
                                     __float2bfloat16(v.y - __bfloat162float(h1)));
    zl2[i4 * 2 + 1] = __nv_bfloat162(__float2bfloat16(v.z - __bfloat162float(h2)),
                                     __float2bfloat16(v.w - __bfloat162float(h3)));
}

// ============================================================================
// Kernel B: W[768][2304] fp32 -> WhT/WlT[2304][768] bf16 (transpose + split).
// ============================================================================
__global__ void convert_w_kernel(const float* __restrict__ W)
{
    __shared__ float t[32][33];
    const int n0 = blockIdx.x * 32;
    const int k0 = blockIdx.y * 32;
    const int tx = threadIdx.x, ty = threadIdx.y;   // 32 x 8
#pragma unroll
    for (int i = 0; i < 4; i++)
        t[ty + 8 * i][tx] = W[(size_t)(k0 + ty + 8 * i) * NCOL + n0 + tx];
    __syncthreads();
#pragma unroll
    for (int i = 0; i < 4; i++) {
        float v = t[tx][ty + 8 * i];
        __nv_bfloat16 h = __float2bfloat16(v);
        size_t o = (size_t)(n0 + ty + 8 * i) * EMB + k0 + tx;
        g_WhT[o] = h;
        g_WlT[o] = __float2bfloat16(v - __bfloat162float(h));
    }
}

// ============================================================================
// Kernel C: QKV GEMM via HMMA, bf16x3 (AhBh + AhBl + AlBh).
// CTA 128x128, 8 warps (2M x 4N), warp tile 64x32. K=768, chunks of 64.
// Epilogue: + bias, split to bf16 hi/lo, scatter to Q/K ([n][d]) and VT ([d][n]).
// ============================================================================
#define AP 72   // smem pitch in bf16

__global__ __launch_bounds__(256, 1)
void qkv_mma_kernel(const float* __restrict__ bias)
{
    extern __shared__ __nv_bfloat16 smb[];
    __nv_bfloat16* sAh = smb;
    __nv_bfloat16* sAl = smb + 128 * AP;
    __nv_bfloat16* sBh = smb + 2 * 128 * AP;
    __nv_bfloat16* sBl = smb + 3 * 128 * AP;

    const int tid  = threadIdx.x;
    const int lane = tid & 31;
    const int wid  = tid >> 5;
    const int wm = (wid >> 2) << 6;
    const int wn = (wid & 3) << 5;
    const int m0 = blockIdx.y * 128;
    const int n0 = blockIdx.x * 128;

    const uint32_t uAh = smem_u32(sAh), uAl = smem_u32(sAl);
    const uint32_t uBh = smem_u32(sBh), uBl = smem_u32(sBl);

    float acc[4][4][4];
#pragma unroll
    for (int mt = 0; mt < 4; mt++)
#pragma unroll
        for (int nt = 0; nt < 4; nt++)
#pragma unroll
            for (int e = 0; e < 4; e++) acc[mt][nt][e] = 0.f;

    const uint32_t a_off = (uint32_t)((wm + (lane & 15)) * AP + ((lane >> 4) << 3)) * 2;
    const uint32_t b_off = (uint32_t)((wn + (lane & 7)) * AP + (((lane >> 3) & 1) << 3)) * 2;

    for (int kc = 0; kc < 12; kc++) {
        const int kb = kc * 64;
        __syncthreads();
#pragma unroll
        for (int j = 0; j < 4; j++) {
            int idx = tid + j * 256;
            int r = idx >> 3, c = idx & 7;
            size_t ga = (size_t)(m0 + r) * EMB + kb + c * 8;
            size_t gb = (size_t)(n0 + r) * EMB + kb + c * 8;
            uint32_t so = (uint32_t)(r * AP + c * 8) * 2;
            *(uint4*)((char*)sAh + so) = *(const uint4*)&g_zh[ga];
            *(uint4*)((char*)sAl + so) = *(const uint4*)&g_zl[ga];
            *(uint4*)((char*)sBh + so) = *(const uint4*)&g_WhT[gb];
            *(uint4*)((char*)sBl + so) = *(const uint4*)&g_WlT[gb];
        }
        __syncthreads();

#pragma unroll
        for (int ks = 0; ks < 4; ks++) {
            const uint32_t kof = (uint32_t)(ks * 16) * 2;
            uint32_t ah[4][4], al[4][4], bh[4][2], bl[4][2];
#pragma unroll
            for (int mt = 0; mt < 4; mt++) {
                uint32_t ad = a_off + kof + (uint32_t)(mt * 16 * AP) * 2;
                LDM_X4(ah[mt], uAh + ad);
                LDM_X4(al[mt], uAl + ad);
            }
#pragma unroll
            for (int nt = 0; nt < 4; nt++) {
                uint32_t bd = b_off + kof + (uint32_t)(nt * 8 * AP) * 2;
                LDM_X2(bh[nt], uBh + bd);
                LDM_X2(bl[nt], uBl + bd);
            }
#pragma unroll
            for (int mt = 0; mt < 4; mt++)
#pragma unroll
                for (int nt = 0; nt < 4; nt++) {
                    MMA_BF16(acc[mt][nt], ah[mt], bh[nt]);
                    MMA_BF16(acc[mt][nt], ah[mt], bl[nt]);
                    MMA_BF16(acc[mt][nt], al[mt], bh[nt]);
                }
        }
    }

    // Epilogue: bias + bf16 split + scatter.
    const int g = lane >> 2;
    const int t2 = (lane & 3) << 1;
#pragma unroll
    for (int mt = 0; mt < 4; mt++) {
#pragma unroll
        for (int e2i = 0; e2i < 2; e2i++) {
            int mrow = m0 + wm + mt * 16 + g + e2i * 8;
            int bb = mrow >> 11;
            int nn = mrow & 2047;
            size_t bhf_base = (size_t)(bb * NH);
#pragma unroll
            for (int nt = 0; nt < 4; nt++) {
#pragma unroll
                for (int u = 0; u < 2; u++) {
                    int c = n0 + wn + nt * 8 + t2 + u;
                    float v = acc[mt][nt][e2i * 2 + u] + bias[c];
                    int h = c / 192;
                    int rem = c - h * 192;
                    int d = rem / 3;
                    int s = rem - d * 3;
                    size_t bhf = bhf_base + h;
                    __nv_bfloat16 vh = __float2bfloat16(v);
                    __nv_bfloat16 vl = __float2bfloat16(v - __bfloat162float(vh));
                    if (s == 0) {
                        size_t idx = (bhf * SEQ + nn) * HD + d;
                        g_Kh[idx] = vh; g_Kl[idx] = vl;
                    } else if (s == 1) {
                        size_t idx = (bhf * HD + d) * SEQ + nn;
                        g_VTh[idx] = vh; g_VTl[idx] = vl;
                    } else {
                        size_t idx = (bhf * SEQ + nn) * HD + d;
                        g_Qh[idx] = vh; g_Ql[idx] = vl;
                    }
                }
            }
        }
    }
}

// ============================================================================
// Kernel D: attention via HMMA bf16x3. 128 threads, 4 warps x 16q, BN=64.
// S-fragments exp'd in registers and re-used directly as PV A-fragments.
// No-max softmax (logits bounded, shift cancels in O/l). Reference bug:
// 1/sqrt(D)=0.125 applied AFTER softmax -> folded into the final store.
// Smem: Qh,Ql,Kh,Kl,VTh,VTl tiles [64][72] bf16 = 54 KB.
// ============================================================================
#define AT 72

__global__ __launch_bounds__(128)
void attn_hmma_kernel(float* __restrict__ out)
{
    extern __shared__ __nv_bfloat16 sb[];
    __nv_bfloat16* sQh = sb;
    __nv_bfloat16* sQl = sb + 64 * AT;
    __nv_bfloat16* sKh = sb + 2 * 64 * AT;
    __nv_bfloat16* sKl = sb + 3 * 64 * AT;
    __nv_bfloat16* sVh = sb + 4 * 64 * AT;
    __nv_bfloat16* sVl = sb + 5 * 64 * AT;

    const int tid = threadIdx.x;
    const int lane = tid & 31;
    const int wq = tid >> 5;           // warp's 16-q slice
    const int q0 = blockIdx.x << 6;
    const int bh = blockIdx.y;

    const __nv_bfloat16* gQh = g_Qh + (size_t)bh * SEQ * HD;
    const __nv_bfloat16* gQl = g_Ql + (size_t)bh * SEQ * HD;
    const __nv_bfloat16* gKh = g_Kh + (size_t)bh * SEQ * HD;
    const __nv_bfloat16* gKl = g_Kl + (size_t)bh * SEQ * HD;
    const __nv_bfloat16* gVh = g_VTh + (size_t)bh * HD * SEQ;
    const __nv_bfloat16* gVl = g_VTl + (size_t)bh * HD * SEQ;

    const uint32_t uQh = smem_u32(sQh), uQl = smem_u32(sQl);
    const uint32_t uKh = smem_u32(sKh), uKl = smem_u32(sKl);
    const uint32_t uVh = smem_u32(sVh), uVl = smem_u32(sVl);

    // Q tile fill: [64 q][64 d] bf16, 512 uint4 per array.
#pragma unroll
    for (int j = 0; j < 4; j++) {
        int idx = tid + j * 128;
        int r = idx >> 3, c = (idx & 7) * 8;
        uint32_t so = (uint32_t)(r * AT + c) * 2;
        size_t go = (size_t)(q0 + r) * HD + c;
        *(uint4*)((char*)sQh + so) = *(const uint4*)&gQh[go];
        *(uint4*)((char*)sQl + so) = *(const uint4*)&gQl[go];
    }

    // ldmatrix lane offsets (bytes).
    const uint32_t a_off = (uint32_t)((wq * 16 + (lane & 15)) * AT + ((lane >> 4) << 3)) * 2;
    const uint32_t b_off = (uint32_t)((lane & 7) * AT + (((lane >> 3) & 3) << 3)) * 2;

    float oacc[8][4];
#pragma unroll
    for (int j = 0; j < 8; j++)
#pragma unroll
        for (int e = 0; e < 4; e++) oacc[j][e] = 0.f;
    float lsum0 = 0.f, lsum1 = 0.f;

    for (int kt = 0; kt < 32; kt++) {
        const int k0 = kt << 6;
        __syncthreads();
        // K/V tile fills.
#pragma unroll
        for (int j = 0; j < 4; j++) {
            int idx = tid + j * 128;
            int r = idx >> 3, c = (idx & 7) * 8;
            uint32_t so = (uint32_t)(r * AT + c) * 2;
            size_t gk = (size_t)(k0 + r) * HD + c;
            size_t gv = (size_t)r * SEQ + k0 + c;
            *(uint4*)((char*)sKh + so) = *(const uint4*)&gKh[gk];
            *(uint4*)((char*)sKl + so) = *(const uint4*)&gKl[gk];
            *(uint4*)((char*)sVh + so) = *(const uint4*)&gVh[gv];
            *(uint4*)((char*)sVl + so) = *(const uint4*)&gVl[gv];
        }
        __syncthreads();

        // ---- S = Q K^T : warp tile 16q x 64k, 8 n8-fragments. ----
        float sacc[8][4];
#pragma unroll
        for (int j = 0; j < 8; j++)
#pragma unroll
            for (int e = 0; e < 4; e++) sacc[j][e] = 0.f;

#pragma unroll
        for (int bs = 0; bs < 2; bs++) {       // two k32 big-steps over d
            uint32_t ah0[4], al0[4], ah1[4], al1[4];
            LDM_X4(ah0, uQh + a_off + (2 * bs) * 32);
            LDM_X4(al0, uQl + a_off + (2 * bs) * 32);
            LDM_X4(ah1, uQh + a_off + (2 * bs + 1) * 32);
            LDM_X4(al1, uQl + a_off + (2 * bs + 1) * 32);
#pragma unroll
            for (int j = 0; j < 8; j++) {
                uint32_t kh4[4], kl4[4];
                uint32_t bd = b_off + (uint32_t)(j * 8 * AT) * 2 + bs * 64;
                LDM_X4(kh4, uKh + bd);
                LDM_X4(kl4, uKl + bd);
                MMA_BF16(sacc[j], ah0, (kh4 + 0));
                MMA_BF16(sacc[j], ah0, (kl4 + 0));
                MMA_BF16(sacc[j], al0, (kh4 + 0));
                MMA_BF16(sacc[j], ah1, (kh4 + 2));
                MMA_BF16(sacc[j], ah1, (kl4 + 2));
                MMA_BF16(sacc[j], al1, (kh4 + 2));
            }
        }

        // ---- exp + convert C-frags -> PV A-frags (registers only). ----
        uint32_t ph[4][4], pl[4][4];
#pragma unroll
        for (int j = 0; j < 8; j++) {
            float e0 = __expf(sacc[j][0]);
            float e1 = __expf(sacc[j][1]);
            float e2 = __expf(sacc[j][2]);
            float e3 = __expf(sacc[j][3]);
            lsum0 += e0 + e1;
            lsum1 += e2 + e3;
            int t = j >> 1, hf = (j & 1) << 1;
            uint32_t p01 = cvt_bf16x2(e1, e0);
            uint32_t p23 = cvt_bf16x2(e3, e2);
            ph[t][hf + 0] = p01;
            ph[t][hf + 1] = p23;
            float r0 = e0 - __uint_as_float(p01 << 16);
            float r1 = e1 - __uint_as_float(p01 & 0xffff0000u);
            float r2 = e2 - __uint_as_float(p23 << 16);
            float r3 = e3 - __uint_as_float(p23 & 0xffff0000u);
            pl[t][hf + 0] = cvt_bf16x2(r1, r0);
            pl[t][hf + 1] = cvt_bf16x2(r3, r2);
        }

        // ---- O += P V : B = VT[d][k], 8 d-fragments. ----
#pragma unroll
        for (int bs = 0; bs < 2; bs++) {
#pragma unroll
            for (int j = 0; j < 8; j++) {
                uint32_t vh4[4], vl4[4];
                uint32_t bd = b_off + (uint32_t)(j * 8 * AT) * 2 + bs * 64;
                LDM_X4(vh4, uVh + bd);
                LDM_X4(vl4, uVl + bd);
                MMA_BF16(oacc[j], ph[2 * bs], (vh4 + 0));
                MMA_BF16(oacc[j], ph[2 * bs], (vl4 + 0));
                MMA_BF16(oacc[j], pl[2 * bs], (vh4 + 0));
                MMA_BF16(oacc[j], ph[2 * bs + 1], (vh4 + 2));
                MMA_BF16(oacc[j], ph[2 * bs + 1], (vl4 + 2));
                MMA_BF16(oacc[j], pl[2 * bs + 1], (vh4 + 2));
            }
        }
    }

    // ---- Epilogue: reduce l across the 4 lanes sharing each row, scale, store.
#pragma unroll
    for (int off = 1; off < 4; off <<= 1) {
        lsum0 += __shfl_xor_sync(0xffffffffu, lsum0, off);
        lsum1 += __shfl_xor_sync(0xffffffffu, lsum1, off);
    }
    const float inv0 = 0.125f / lsum0;
    const float inv1 = 0.125f / lsum1;

    const int g = lane >> 2;
    const int t2 = (lane & 3) << 1;
    const int b = bh / NH;
    const int h = bh - b * NH;
    const int row0 = q0 + wq * 16 + g;
    float* base0 = out + ((size_t)(b * SEQ + row0)) * EMB + h * HD;
    float* base1 = base0 + (size_t)8 * EMB;
#pragma unroll
    for (int j = 0; j < 8; j++) {
        *(float2*)&base0[j * 8 + t2] = make_float2(oacc[j][0] * inv0, oacc[j][1] * inv0);
        *(float2*)&base1[j * 8 + t2] = make_float2(oacc[j][2] * inv1, oacc[j][3] * inv1);
    }
}

// ============================================================================
extern "C" void kernel_launch(void* const* d_in, const int* in_sizes, int n_in,
                              void* d_out, int out_size)
{
    const float* z = nullptr;
    const float* W = nullptr;
    const float* bias = nullptr;
    for (int i = 0; i < n_in; i++) {
        if (in_sizes[i] == NB * SEQ * EMB)      z = (const float*)d_in[i];
        else if (in_sizes[i] == EMB * NCOL)     W = (const float*)d_in[i];
        else if (in_sizes[i] == NCOL)           bias = (const float*)d_in[i];
    }
    float* out = (float*)d_out;

    convert_z_kernel<<<(MROWS * EMB / 4) / 256, 256>>>(z);
    convert_w_kernel<<<dim3(NCOL / 32, EMB / 32), dim3(32, 8)>>>(W);

    const int mma_smem = 4 * 128 * AP * (int)sizeof(__nv_bfloat16);  // 73728
    cudaFuncSetAttribute(qkv_mma_kernel, cudaFuncAttributeMaxDynamicSharedMemorySize,
                         mma_smem);
    qkv_mma_kernel<<<dim3(NCOL / 128, MROWS / 128), 256, mma_smem>>>(bias);

    const int attn_smem = 6 * 64 * AT * (int)sizeof(__nv_bfloat16);  // 55296
    cudaFuncSetAttribute(attn_hmma_kernel, cudaFuncAttributeMaxDynamicSharedMemorySize,
                         attn_smem);
    attn_hmma_kernel<<<dim3(SEQ / 64, NB * NH), 128, attn_smem>>>(out);
}